// round 17
// baseline (speedup 1.0000x reference)
#include <cuda_runtime.h>
#include <cuda_fp16.h>
#include <math.h>
#include <stdint.h>

// ---------------- problem constants ----------------
#define B_    8
#define T_    256
#define D_    512
#define W_    32
#define L_    4
#define A_    6
#define H_    8
#define DH    64
#define NSEQ  (B_*T_)        // 2048
#define MROWS (NSEQ*W_)      // 65536
#define D3    (3*D_)         // 1536
#define DF    (4*D_)         // 2048
#define MFP   2176           // stacked layer-0 rows: 2048 feats + 128 pos

#define BKH   64             // K halves per chunk (128B per row)
#define RS    72             // smem row stride in halves (144B, ldmatrix conflict-free)
#define CHB   (128*RS*2)     // 18432 B per matrix tile
#define STG   (2*CHB)        // 36864 B per stage
#define NSTAGE 3
#define HGEMM_SMEM (NSTAGE*STG)   // 110592 B

// converted-weight offsets (halves) — order matches cvtall segments
#define OFF_WQKV 0
#define OFF_WO   ((size_t)L_*D3*D_)
#define OFF_W1   (OFF_WO + (size_t)L_*D_*D_)
#define OFF_W2   (OFF_W1 + (size_t)L_*DF*D_)
#define WC_TOTAL (OFF_W2 + (size_t)L_*D_*DF)

#define N8_WQKV (L_*D3*D_/8)
#define N8_WO   (L_*D_*D_/8)
#define N8_W1   (L_*DF*D_/8)
#define N8_W2   (L_*D_*DF/8)
#define N8_WTOT (N8_WQKV+N8_WO+N8_W1+N8_W2)
#define N8_FE   (NSEQ*D_/8)
#define N8_PO   (W_*D_/8)

// ---------------- scratch (device globals; no allocations) ----------------
__device__ __align__(16) __half g_X   [(size_t)MROWS * D_];   // fp16 activations
__device__ __align__(16) __half g_QKV [(size_t)MROWS * D3];   // fp16 qkv (layers 1-2) / layer-3 KV
__device__ __align__(16) __half g_H   [(size_t)MROWS * DF];   // fp16 ctx / ff hidden
__device__ __align__(16) __half g_PRE [(size_t)MROWS * D_];   // fp16 preLN
__device__ __align__(16) __half g_Wc  [WC_TOTAL];             // fp16 weights
__device__ __align__(16) __half g_FP  [(size_t)MFP * D_];     // stacked feats(2048)+pos(32), rest 0
__device__ __align__(16) __half g_F   [(size_t)MFP * D3];     // layer0 [F;P] (L2-resident); layer3 Qc
__device__ float g_zerob[D3];                                 // zero bias (static zero-init)

// ---------------- PTX helpers ----------------
__device__ __forceinline__ uint32_t smem_u32(const void* p) {
    uint32_t a;
    asm("{ .reg .u64 t; cvta.to.shared.u64 t, %1; cvt.u32.u64 %0, t; }" : "=r"(a) : "l"(p));
    return a;
}
__device__ __forceinline__ void cp16(uint32_t s, const void* g) {
    asm volatile("cp.async.cg.shared.global [%0], [%1], 16;" :: "r"(s), "l"(g));
}
__device__ __forceinline__ void cp_commit() {
    asm volatile("cp.async.commit_group;" ::: "memory");
}
__device__ __forceinline__ void cp_wait1() { asm volatile("cp.async.wait_group 1;" ::: "memory"); }
__device__ __forceinline__ void cp_wait0() { asm volatile("cp.async.wait_group 0;" ::: "memory"); }

__device__ __forceinline__ void ldm_x4(uint32_t r[4], uint32_t addr) {
    asm volatile("ldmatrix.sync.aligned.m8n8.x4.shared.b16 {%0,%1,%2,%3}, [%4];"
                 : "=r"(r[0]), "=r"(r[1]), "=r"(r[2]), "=r"(r[3]) : "r"(addr));
}
__device__ __forceinline__ void mma_f16(float4& c, const uint32_t a[4], const uint32_t b0, const uint32_t b1) {
    asm volatile(
        "mma.sync.aligned.m16n8k16.row.col.f32.f16.f16.f32 "
        "{%0,%1,%2,%3}, {%4,%5,%6,%7}, {%8,%9}, {%0,%1,%2,%3};"
        : "+f"(c.x), "+f"(c.y), "+f"(c.z), "+f"(c.w)
        : "r"(a[0]), "r"(a[1]), "r"(a[2]), "r"(a[3]), "r"(b0), "r"(b1));
}

__device__ __forceinline__ void st2(float* p, float x, float y)  { *(float2*)p = make_float2(x, y); }
__device__ __forceinline__ void st2(__half* p, float x, float y) { *(__half2*)p = __floats2half2_rn(x, y); }
__device__ __forceinline__ float2 ld2(const float* p)  { return *(const float2*)p; }
__device__ __forceinline__ float2 ld2(const __half* p) { return __half22float2(*(const __half2*)p); }

__device__ __forceinline__ void cvt8(const float* s, __half* d) {
    const float4 a = *(const float4*)s;
    const float4 b = *(const float4*)(s + 4);
    __half2 h[4];
    h[0] = __floats2half2_rn(a.x, a.y);
    h[1] = __floats2half2_rn(a.z, a.w);
    h[2] = __floats2half2_rn(b.x, b.y);
    h[3] = __floats2half2_rn(b.z, b.w);
    *(uint2*)d       = *(uint2*)&h[0];
    *(uint2*)(d + 4) = *(uint2*)&h[2];
}

// ---------------- merged weight conversion ----------------
__global__ __launch_bounds__(256)
void cvtall_k(const float* __restrict__ wqkv, const float* __restrict__ wo,
              const float* __restrict__ w1,   const float* __restrict__ w2)
{
    int i = blockIdx.x * 256 + threadIdx.x;
    const float* src;
    size_t so;
    if      (i < N8_WQKV)                 { src = wqkv; so = i; }
    else if (i < N8_WQKV + N8_WO)         { src = wo;   so = i - N8_WQKV; }
    else if (i < N8_WQKV + N8_WO + N8_W1) { src = w1;   so = i - N8_WQKV - N8_WO; }
    else                                  { src = w2;   so = i - N8_WQKV - N8_WO - N8_W1; }
    cvt8(src + so * 8, g_Wc + (size_t)i * 8);
}

// ---------------- feats+pos conversion into stacked buffer ----------------
__global__ __launch_bounds__(256)
void cvtfp_k(const float* __restrict__ feats, const float* __restrict__ pos)
{
    int i = blockIdx.x * 256 + threadIdx.x;
    if (i >= N8_FE + N8_PO) return;
    if (i < N8_FE) cvt8(feats + (size_t)i * 8, g_FP + (size_t)i * 8);
    else {
        int j = i - N8_FE;
        cvt8(pos + (size_t)j * 8, g_FP + (size_t)2048 * D_ + (size_t)j * 8);
    }
}

// ---------------- gather w=31 rows of X into compact Xc (2048 x 512) ----------------
__global__ __launch_bounds__(256)
void gather31_k(const __half* __restrict__ X, __half* __restrict__ Xc)
{
    int idx = blockIdx.x * 256 + threadIdx.x;
    int d8  = idx & 63;
    int seq = idx >> 6;
    const __half* src = X + ((size_t)(seq * W_ + (W_ - 1))) * D_ + d8 * 8;
    __half* dst = Xc + (size_t)seq * D_ + d8 * 8;
    *(uint2*)dst       = *(const uint2*)src;
    *(uint2*)(dst + 4) = *(const uint2*)(src + 4);
}

// ---------------- fp16 mma.sync GEMM (128x128 tile, BK=64, 3-stage, 1 barrier/chunk) -----------
// WIN=1: residual computed on the fly as feats[frame(m)][n] + pos[w(m)][n] (fp32 inputs).
template<int RELU, int WIN, typename TC, typename TR>
__global__ __launch_bounds__(256, 2)
void hgemm_k(const __half* __restrict__ A, const __half* __restrict__ Bw,
             const float* __restrict__ bias, const TR* __restrict__ resid,
             const float* __restrict__ pos,
             TC* __restrict__ C, int M, int N, int K)
{
    extern __shared__ __half sh[];
    const uint32_t sm0 = smem_u32(sh);

    const int tid  = threadIdx.x;
    const int lane = tid & 31;
    const int wid  = tid >> 5;
    const int wm   = wid >> 2;
    const int wn   = wid & 3;
    const int l4   = lane >> 2;
    const int lm   = lane & 3;
    const int n0   = blockIdx.x * 128;
    const int m0   = blockIdx.y * 128;

    const int row0 = tid >> 3;
    const int prt0 = tid & 7;
    const __half* Au = A  + (size_t)(m0 + row0) * K + prt0 * 8;
    const __half* Bu = Bw + (size_t)(n0 + row0) * K + prt0 * 8;
    const uint32_t du = (uint32_t)(row0 * RS + prt0 * 8) * 2;

    auto stage = [&](int c) {
        uint32_t base = sm0 + (uint32_t)(c % NSTAGE) * STG;
        const size_t ko = (size_t)c * BKH;
#pragma unroll
        for (int i = 0; i < 4; i++) {
            cp16(base + du + i * 32 * RS * 2,       Au + (size_t)(i * 32) * K + ko);
            cp16(base + CHB + du + i * 32 * RS * 2, Bu + (size_t)(i * 32) * K + ko);
        }
        cp_commit();
    };

    const int rA   = lane & 15;
    const int kofA = (lane >> 4) * 8;
    const int rB   = lane & 7;
    const int kofB = ((lane >> 3) & 1) * 8;
    const int whB  = (lane >> 4) * 8;

    const uint32_t aoffs = (uint32_t)((wm * 64 + rA) * RS + kofA) * 2;
    const uint32_t boffs = (uint32_t)CHB + (uint32_t)((wn * 32 + whB + rB) * RS + kofB) * 2;

    float4 acc[4][4];
#pragma unroll
    for (int i = 0; i < 4; i++)
#pragma unroll
        for (int j = 0; j < 4; j++) acc[i][j] = make_float4(0.f, 0.f, 0.f, 0.f);

    const int nchunk = K / BKH;
    stage(0); stage(1);

    uint32_t af[2][4][4], bf[2][2][4];

    for (int c = 0; c < nchunk; c++) {
        if (c + 1 < nchunk) cp_wait1();
        else                cp_wait0();
        __syncthreads();
        if (c + 2 < nchunk) stage(c + 2);

        const uint32_t base = sm0 + (uint32_t)(c % NSTAGE) * STG;

#pragma unroll
        for (int mt = 0; mt < 4; mt++)
            ldm_x4(af[0][mt], base + aoffs + (uint32_t)(mt * 16 * RS) * 2);
#pragma unroll
        for (int ntp = 0; ntp < 2; ntp++)
            ldm_x4(bf[0][ntp], base + boffs + (uint32_t)(ntp * 16 * RS) * 2);

#pragma unroll
        for (int ks = 0; ks < 4; ks++) {
            const int cur = ks & 1, nxt = cur ^ 1;
            if (ks < 3) {
                const uint32_t ko = (uint32_t)((ks + 1) * 16) * 2;
#pragma unroll
                for (int mt = 0; mt < 4; mt++)
                    ldm_x4(af[nxt][mt], base + aoffs + (uint32_t)(mt * 16 * RS) * 2 + ko);
#pragma unroll
                for (int ntp = 0; ntp < 2; ntp++)
                    ldm_x4(bf[nxt][ntp], base + boffs + (uint32_t)(ntp * 16 * RS) * 2 + ko);
            }
#pragma unroll
            for (int mt = 0; mt < 4; mt++)
#pragma unroll
                for (int nt = 0; nt < 4; nt++)
                    mma_f16(acc[mt][nt], af[cur][mt],
                            bf[cur][nt >> 1][(nt & 1) * 2], bf[cur][nt >> 1][(nt & 1) * 2 + 1]);
        }
    }

    __syncthreads();

    auto winres = [&](int mm, int nn) -> float2 {
        int w = mm & 31, seq = mm >> 5, t = seq & (T_ - 1);
        int f = t + 1 - W_ + w; if (f < 0) f = 0;
        int frame = (seq - t) + f;
        float2 a = ld2((const float*)resid + (size_t)frame * D_ + nn);
        float2 p = ld2(pos + (size_t)w * D_ + nn);
        return make_float2(a.x + p.x, a.y + p.y);
    };

#pragma unroll
    for (int mt = 0; mt < 4; mt++) {
        const int m = m0 + wm * 64 + mt * 16 + l4;
#pragma unroll
        for (int nt = 0; nt < 4; nt++) {
            const int n = n0 + wn * 32 + nt * 8 + lm * 2;
            float4 cc = acc[mt][nt];
            float2 bv = *(const float2*)(bias + n);
            cc.x += bv.x; cc.y += bv.y;
            cc.z += bv.x; cc.w += bv.y;
            if (WIN) {
                float2 r0 = winres(m, n);
                float2 r1 = winres(m + 8, n);
                cc.x += r0.x; cc.y += r0.y;
                cc.z += r1.x; cc.w += r1.y;
            } else if (resid) {
                float2 r0 = ld2(resid + (size_t)m * N + n);
                float2 r1 = ld2(resid + (size_t)(m + 8) * N + n);
                cc.x += r0.x; cc.y += r0.y;
                cc.z += r1.x; cc.w += r1.y;
            }
            if (RELU) {
                cc.x = fmaxf(cc.x, 0.f); cc.y = fmaxf(cc.y, 0.f);
                cc.z = fmaxf(cc.z, 0.f); cc.w = fmaxf(cc.w, 0.f);
            }
            st2(C + (size_t)m * N + n,       cc.x, cc.y);
            st2(C + (size_t)(m + 8) * N + n, cc.z, cc.w);
        }
    }
}

// ---------------- layer-0 attention fused with qkv gather: reads compact F (L2-resident) --------
__global__ __launch_bounds__(32)
void attn0_k(const __half* __restrict__ F, const float* __restrict__ bq,
             __half* __restrict__ ctx)
{
    const int sh   = blockIdx.x;
    const int seq  = sh >> 3;
    const int h    = sh & 7;
    const int lane = threadIdx.x;
    const int t    = seq & (T_ - 1);
    const int sb   = seq - t;

    __shared__ uint2 ks[W_][16], vs[W_][16];

#pragma unroll
    for (int i = 0; i < 16; i++) {
        int idx = i * 32 + lane;
        int row = idx >> 4, c4 = idx & 15;
        int f = t + 1 - W_ + row; if (f < 0) f = 0;
        int frame = sb + f;
        int off = h * DH + c4 * 4;
        const __half* fk = F + (size_t)frame * D3 + 512 + off;
        const __half* pk = F + (size_t)(2048 + row) * D3 + 512 + off;
        const float*  bk = bq + 512 + off;
        float2 a0 = ld2(fk), a1 = ld2(fk + 2);
        float2 p0 = ld2(pk), p1 = ld2(pk + 2);
        float4 bb = *(const float4*)bk;
        __half2 h0 = __floats2half2_rn(a0.x + p0.x + bb.x, a0.y + p0.y + bb.y);
        __half2 h1 = __floats2half2_rn(a1.x + p1.x + bb.z, a1.y + p1.y + bb.w);
        uint2 kk; kk.x = *(uint32_t*)&h0; kk.y = *(uint32_t*)&h1;
        ks[row][c4] = kk;
        a0 = ld2(fk + 512); a1 = ld2(fk + 514);
        p0 = ld2(pk + 512); p1 = ld2(pk + 514);
        float4 b2 = *(const float4*)(bk + 512);
        h0 = __floats2half2_rn(a0.x + p0.x + b2.x, a0.y + p0.y + b2.y);
        h1 = __floats2half2_rn(a1.x + p1.x + b2.z, a1.y + p1.y + b2.w);
        uint2 vv; vv.x = *(uint32_t*)&h0; vv.y = *(uint32_t*)&h1;
        vs[row][c4] = vv;
    }
    // q row = lane (fp32, unrounded)
    float4 q[16];
    {
        int f = t + 1 - W_ + lane; if (f < 0) f = 0;
        int frame = sb + f;
        const __half* fq = F + (size_t)frame * D3 + h * DH;
        const __half* pq = F + (size_t)(2048 + lane) * D3 + h * DH;
        const float*  bp = bq + h * DH;
#pragma unroll
        for (int i = 0; i < 16; i++) {
            float2 a0 = ld2(fq + i * 4), a1 = ld2(fq + i * 4 + 2);
            float2 p0 = ld2(pq + i * 4), p1 = ld2(pq + i * 4 + 2);
            float4 bb = *(const float4*)(bp + i * 4);
            q[i] = make_float4(a0.x + p0.x + bb.x, a0.y + p0.y + bb.y,
                               a1.x + p1.x + bb.z, a1.y + p1.y + bb.w);
        }
    }
    __syncwarp();

    float sc[W_];
#pragma unroll
    for (int c = 0; c < W_; c++) {
        float s = 0.f;
#pragma unroll
        for (int e = 0; e < 16; e++) {
            uint2 kk = ks[c][e];
            float2 k0 = __half22float2(*(__half2*)&kk.x);
            float2 k1 = __half22float2(*(__half2*)&kk.y);
            s += q[e].x * k0.x + q[e].y * k0.y + q[e].z * k1.x + q[e].w * k1.y;
        }
        sc[c] = (c <= lane) ? s * 0.125f : -1e30f;
    }

    float mx = -1e30f;
#pragma unroll
    for (int c = 0; c < W_; c++) mx = fmaxf(mx, sc[c]);
    float sum = 0.f;
#pragma unroll
    for (int c = 0; c < W_; c++) { float e = expf(sc[c] - mx); sc[c] = e; sum += e; }
    float inv = 1.f / sum;

    float4 acc[16];
#pragma unroll
    for (int e = 0; e < 16; e++) acc[e] = make_float4(0.f, 0.f, 0.f, 0.f);
#pragma unroll
    for (int c = 0; c < W_; c++) {
        float p = sc[c] * inv;
#pragma unroll
        for (int e = 0; e < 16; e++) {
            uint2 vv = vs[c][e];
            float2 v0 = __half22float2(*(__half2*)&vv.x);
            float2 v1 = __half22float2(*(__half2*)&vv.y);
            acc[e].x += p * v0.x; acc[e].y += p * v0.y;
            acc[e].z += p * v1.x; acc[e].w += p * v1.y;
        }
    }

    __half* dst = ctx + ((size_t)seq * W_ + lane) * D_ + h * DH;
#pragma unroll
    for (int e = 0; e < 16; e++) {
        *(__half2*)(dst + e * 4)     = __floats2half2_rn(acc[e].x, acc[e].y);
        *(__half2*)(dst + e * 4 + 2) = __floats2half2_rn(acc[e].z, acc[e].w);
    }
}

// ---------------- attention (layers 1-2): one warp per (seq, head); packed-half smem ------------
__global__ __launch_bounds__(32)
void attn_k(const __half* __restrict__ qkv, __half* __restrict__ ctx)
{
    const int sh   = blockIdx.x;
    const int seq  = sh >> 3;
    const int h    = sh & 7;
    const int lane = threadIdx.x;

    __shared__ uint2 ks[W_][16], vs[W_][16];

    const __half* base = qkv + (size_t)seq * W_ * D3 + h * DH;

#pragma unroll
    for (int i = 0; i < 16; i++) {
        int idx = i * 32 + lane;
        int row = idx >> 4, c4 = idx & 15;
        const __half* src = base + (size_t)row * D3 + c4 * 4;
        ks[row][c4] = *(const uint2*)(src + 512);
        vs[row][c4] = *(const uint2*)(src + 1024);
    }
    float4 q[16];
    {
        const __half* qr = base + (size_t)lane * D3;
#pragma unroll
        for (int i = 0; i < 16; i++) {
            float2 a = ld2(qr + i * 4);
            float2 b = ld2(qr + i * 4 + 2);
            q[i] = make_float4(a.x, a.y, b.x, b.y);
        }
    }
    __syncwarp();

    float sc[W_];
#pragma unroll
    for (int c = 0; c < W_; c++) {
        float s = 0.f;
#pragma unroll
        for (int e = 0; e < 16; e++) {
            uint2 kk = ks[c][e];
            float2 k0 = __half22float2(*(__half2*)&kk.x);
            float2 k1 = __half22float2(*(__half2*)&kk.y);
            s += q[e].x * k0.x + q[e].y * k0.y + q[e].z * k1.x + q[e].w * k1.y;
        }
        sc[c] = (c <= lane) ? s * 0.125f : -1e30f;
    }

    float mx = -1e30f;
#pragma unroll
    for (int c = 0; c < W_; c++) mx = fmaxf(mx, sc[c]);
    float sum = 0.f;
#pragma unroll
    for (int c = 0; c < W_; c++) { float e = expf(sc[c] - mx); sc[c] = e; sum += e; }
    float inv = 1.f / sum;

    float4 acc[16];
#pragma unroll
    for (int e = 0; e < 16; e++) acc[e] = make_float4(0.f, 0.f, 0.f, 0.f);
#pragma unroll
    for (int c = 0; c < W_; c++) {
        float p = sc[c] * inv;
#pragma unroll
        for (int e = 0; e < 16; e++) {
            uint2 vv = vs[c][e];
            float2 v0 = __half22float2(*(__half2*)&vv.x);
            float2 v1 = __half22float2(*(__half2*)&vv.y);
            acc[e].x += p * v0.x; acc[e].y += p * v0.y;
            acc[e].z += p * v1.x; acc[e].w += p * v1.y;
        }
    }

    __half* dst = ctx + ((size_t)seq * W_ + lane) * D_ + h * DH;
#pragma unroll
    for (int e = 0; e < 16; e++) {
        *(__half2*)(dst + e * 4)     = __floats2half2_rn(acc[e].x, acc[e].y);
        *(__half2*)(dst + e * 4 + 2) = __floats2half2_rn(acc[e].z, acc[e].w);
    }
}

// ---------------- layer-3 attention: only row w=31; kv row stride 1024 ----------------
__global__ __launch_bounds__(32)
void attn3_k(const __half* __restrict__ kv, const __half* __restrict__ qc,
             __half* __restrict__ ctxc)
{
    const int sh   = blockIdx.x;
    const int seq  = sh >> 3;
    const int h    = sh & 7;
    const int lane = threadIdx.x;

    __shared__ float qs[DH];
    __shared__ float ps[W_];

    const __half* qp = qc + (size_t)seq * D_ + h * DH;
    float2 qv = ld2(qp + lane * 2);
    qs[lane * 2] = qv.x; qs[lane * 2 + 1] = qv.y;
    __syncwarp();

    const __half* kp = kv + ((size_t)seq * W_ + lane) * 1024 + h * DH;
    float s = 0.f;
#pragma unroll
    for (int e = 0; e < DH; e += 2) {
        float2 kk = ld2(kp + e);
        s += qs[e] * kk.x + qs[e + 1] * kk.y;
    }
    s *= 0.125f;

    float mx = s;
#pragma unroll
    for (int o = 16; o; o >>= 1) mx = fmaxf(mx, __shfl_xor_sync(0xffffffffu, mx, o));
    float e = expf(s - mx), sum = e;
#pragma unroll
    for (int o = 16; o; o >>= 1) sum += __shfl_xor_sync(0xffffffffu, sum, o);
    ps[lane] = e / sum;
    __syncwarp();

    float a0 = 0.f, a1 = 0.f;
    const __half* vp = kv + (size_t)seq * W_ * 1024 + 512 + h * DH + lane * 2;
#pragma unroll
    for (int c = 0; c < W_; c++) {
        float2 vv = ld2(vp + (size_t)c * 1024);
        a0 += ps[c] * vv.x; a1 += ps[c] * vv.y;
    }
    *(__half2*)(ctxc + (size_t)seq * D_ + h * DH + lane * 2) = __floats2half2_rn(a0, a1);
}

// ---------------- LayerNorm: warp per row; fp16 in -> fp16 out ----------------
__global__ __launch_bounds__(256)
void ln_k(const __half* __restrict__ in, const float* __restrict__ g,
          const float* __restrict__ b, __half* __restrict__ out)
{
    const int row  = blockIdx.x * 8 + (threadIdx.x >> 5);
    const int lane = threadIdx.x & 31;
    const __half* x = in + (size_t)row * D_ + lane * 16;

    uint4 r0 = *(const uint4*)x;
    uint4 r1 = *(const uint4*)(x + 8);
    float v[16];
    {
        uint32_t uu[8] = {r0.x, r0.y, r0.z, r0.w, r1.x, r1.y, r1.z, r1.w};
#pragma unroll
        for (int k = 0; k < 8; k++) {
            float2 f = __half22float2(*(__half2*)&uu[k]);
            v[2 * k] = f.x; v[2 * k + 1] = f.y;
        }
    }

    float s = 0.f, sq = 0.f;
#pragma unroll
    for (int j = 0; j < 16; j++) { s += v[j]; sq += v[j] * v[j]; }
#pragma unroll
    for (int off = 16; off; off >>= 1) {
        s  += __shfl_xor_sync(0xffffffffu, s,  off);
        sq += __shfl_xor_sync(0xffffffffu, sq, off);
    }
    const float mean = s * (1.f / D_);
    const float rstd = rsqrtf(sq * (1.f / D_) - mean * mean + 1e-5f);

    const float* gp = g + lane * 16;
    const float* bp = b + lane * 16;
    __half2 ho[8];
#pragma unroll
    for (int k = 0; k < 8; k++) {
        float2 gg = *(const float2*)(gp + 2 * k);
        float2 bb = *(const float2*)(bp + 2 * k);
        ho[k] = __floats2half2_rn((v[2 * k]     - mean) * rstd * gg.x + bb.x,
                                  (v[2 * k + 1] - mean) * rstd * gg.y + bb.y);
    }
    __half* o = out + (size_t)row * D_ + lane * 16;
    uint4 w0, w1;
    w0.x = *(uint32_t*)&ho[0]; w0.y = *(uint32_t*)&ho[1];
    w0.z = *(uint32_t*)&ho[2]; w0.w = *(uint32_t*)&ho[3];
    w1.x = *(uint32_t*)&ho[4]; w1.y = *(uint32_t*)&ho[5];
    w1.z = *(uint32_t*)&ho[6]; w1.w = *(uint32_t*)&ho[7];
    *(uint4*)o       = w0;
    *(uint4*)(o + 8) = w1;
}

// ---------------- head: logits (B,T,A) then values (B,T); reads compact Xc ----------------
__global__ __launch_bounds__(256)
void head_k(const __half* __restrict__ xc, const float* __restrict__ Wp,
            const float* __restrict__ bp, const float* __restrict__ Wv,
            const float* __restrict__ bv, float* __restrict__ out)
{
    const int seq = blockIdx.x;
    __shared__ float tok[D_];
    const int tid = threadIdx.x;
    const __half* src = xc + (size_t)seq * D_;
    float2 f = ld2(src + tid * 2);
    tok[tid * 2] = f.x; tok[tid * 2 + 1] = f.y;
    __syncthreads();
    int wid = tid >> 5, lane = tid & 31;
    if (wid < 7) {
        const float* wrow = (wid < 6) ? (Wp + wid * D_) : Wv;
        float s = 0.f;
        for (int i = lane; i < D_; i += 32) s += tok[i] * wrow[i];
#pragma unroll
        for (int off = 16; off; off >>= 1) s += __shfl_down_sync(0xffffffffu, s, off);
        if (lane == 0) {
            if (wid < 6) out[(size_t)seq * A_ + wid] = s + bp[wid];
            else         out[(size_t)NSEQ * A_ + seq] = s + bv[0];
        }
    }
}

// ---------------- launch ----------------
extern "C" void kernel_launch(void* const* d_in, const int* in_sizes, int n_in,
                              void* d_out, int out_size)
{
    const float* feats = (const float*)d_in[0];
    const float* pos   = (const float*)d_in[1];
    const float* Wqkv  = (const float*)d_in[2];
    const float* bqkv  = (const float*)d_in[3];
    const float* Wo    = (const float*)d_in[4];
    const float* bo    = (const float*)d_in[5];
    const float* ln1g  = (const float*)d_in[6];
    const float* ln1b  = (const float*)d_in[7];
    const float* W1    = (const float*)d_in[8];
    const float* b1    = (const float*)d_in[9];
    const float* W2    = (const float*)d_in[10];
    const float* b2    = (const float*)d_in[11];
    const float* ln2g  = (const float*)d_in[12];
    const float* ln2b  = (const float*)d_in[13];
    const float* Wp    = (const float*)d_in[14];
    const float* bp    = (const float*)d_in[15];
    const float* Wv    = (const float*)d_in[16];
    const float* bv    = (const float*)d_in[17];
    float* out = (float*)d_out;

    __half *X, *QKV, *Hb, *Wc, *FP, *F, *PRE;
    float *ZB;
    cudaGetSymbolAddress((void**)&X,   g_X);
    cudaGetSymbolAddress((void**)&QKV, g_QKV);
    cudaGetSymbolAddress((void**)&Hb,  g_H);
    cudaGetSymbolAddress((void**)&PRE, g_PRE);
    cudaGetSymbolAddress((void**)&Wc,  g_Wc);
    cudaGetSymbolAddress((void**)&FP,  g_FP);
    cudaGetSymbolAddress((void**)&F,   g_F);
    cudaGetSymbolAddress((void**)&ZB,  g_zerob);

    // layer-3 compact buffers (reuse scratch whose producers are done by then)
    __half* Xc   = FP;    // 2048 x 512
    __half* Qc   = F;     // 2048 x 512
    __half* CTXc = Hb;    // 2048 x 512
    __half* HIDc = Hb;    // 2048 x 2048 (after CTXc consumed)
    __half* KV   = QKV;   // 65536 x 1024

    static int attr_done = 0;
    if (!attr_done) {
        cudaFuncSetAttribute((const void*)hgemm_k<0,0,__half,__half>, cudaFuncAttributeMaxDynamicSharedMemorySize, HGEMM_SMEM);
        cudaFuncSetAttribute((const void*)hgemm_k<1,0,__half,__half>, cudaFuncAttributeMaxDynamicSharedMemorySize, HGEMM_SMEM);
        cudaFuncSetAttribute((const void*)hgemm_k<0,1,__half,float>,  cudaFuncAttributeMaxDynamicSharedMemorySize, HGEMM_SMEM);
        attr_done = 1;
    }

    cvtall_k<<<N8_WTOT / 256, 256>>>(Wqkv, Wo, W1, W2);
    cvtfp_k<<<(N8_FE + N8_PO + 255) / 256, 256>>>(feats, pos);

    // ---- layer 0 (factored QKV; attention fused with gather) ----
    hgemm_k<0,0,__half,__half><<<dim3(D3 / 128, MFP / 128), 256, HGEMM_SMEM>>>(
        FP, Wc + OFF_WQKV, ZB, nullptr, nullptr, F, MFP, D3, D_);
    attn0_k<<<NSEQ * H_, 32>>>(F, bqkv, Hb);
    // preLN1(fp16) = (feats[frame]+pos[w]) + ctx @ Wo0^T + bo0
    hgemm_k<0,1,__half,float><<<dim3(D_ / 128, MROWS / 128), 256, HGEMM_SMEM>>>(
        Hb, Wc + OFF_WO, bo, feats, pos, PRE, MROWS, D_, D_);
    ln_k<<<MROWS / 8, 256>>>(PRE, ln1g, ln1b, X);
    hgemm_k<1,0,__half,__half><<<dim3(DF / 128, MROWS / 128), 256, HGEMM_SMEM>>>(
        X, Wc + OFF_W1, b1, nullptr, nullptr, Hb, MROWS, DF, D_);
    hgemm_k<0,0,__half,__half><<<dim3(D_ / 128, MROWS / 128), 256, HGEMM_SMEM>>>(
        Hb, Wc + OFF_W2, b2, X, nullptr, PRE, MROWS, D_, DF);
    ln_k<<<MROWS / 8, 256>>>(PRE, ln2g, ln2b, X);

    // ---- layers 1..2: full pipeline ----
    for (int i = 1; i < L_ - 1; i++) {
        hgemm_k<0,0,__half,__half><<<dim3(D3 / 128, MROWS / 128), 256, HGEMM_SMEM>>>(
            X, Wc + OFF_WQKV + (size_t)i * D3 * D_, bqkv + i * D3, nullptr, nullptr, QKV, MROWS, D3, D_);
        attn_k<<<NSEQ * H_, 32>>>(QKV, Hb);
        hgemm_k<0,0,__half,__half><<<dim3(D_ / 128, MROWS / 128), 256, HGEMM_SMEM>>>(
            Hb, Wc + OFF_WO + (size_t)i * D_ * D_, bo + i * D_, X, nullptr, PRE, MROWS, D_, D_);
        ln_k<<<MROWS / 8, 256>>>(PRE, ln1g + i * D_, ln1b + i * D_, X);
        hgemm_k<1,0,__half,__half><<<dim3(DF / 128, MROWS / 128), 256, HGEMM_SMEM>>>(
            X, Wc + OFF_W1 + (size_t)i * DF * D_, b1 + i * DF, nullptr, nullptr, Hb, MROWS, DF, D_);
        hgemm_k<0,0,__half,__half><<<dim3(D_ / 128, MROWS / 128), 256, HGEMM_SMEM>>>(
            Hb, Wc + OFF_W2 + (size_t)i * D_ * DF, b2 + i * D_, X, nullptr, PRE, MROWS, D_, DF);
        ln_k<<<MROWS / 8, 256>>>(PRE, ln2g + i * D_, ln2b + i * D_, X);
    }

    // ---- layer 3: only the w=31 rows survive into the head ----
    {
        const int i = L_ - 1;    // 3
        hgemm_k<0,0,__half,__half><<<dim3(1024 / 128, MROWS / 128), 256, HGEMM_SMEM>>>(
            X, Wc + OFF_WQKV + (size_t)i * D3 * D_ + (size_t)D_ * D_,
            bqkv + i * D3 + D_, nullptr, nullptr, KV, MROWS, 1024, D_);
        gather31_k<<<(NSEQ * 64) / 256, 256>>>(X, Xc);
        hgemm_k<0,0,__half,__half><<<dim3(D_ / 128, NSEQ / 128), 256, HGEMM_SMEM>>>(
            Xc, Wc + OFF_WQKV + (size_t)i * D3 * D_, bqkv + i * D3, nullptr, nullptr, Qc, NSEQ, D_, D_);
        attn3_k<<<NSEQ * H_, 32>>>(KV, Qc, CTXc);
        hgemm_k<0,0,__half,__half><<<dim3(D_ / 128, NSEQ / 128), 256, HGEMM_SMEM>>>(
            CTXc, Wc + OFF_WO + (size_t)i * D_ * D_, bo + i * D_, Xc, nullptr, PRE, NSEQ, D_, D_);
        ln_k<<<NSEQ / 8, 256>>>(PRE, ln1g + i * D_, ln1b + i * D_, Xc);
        hgemm_k<1,0,__half,__half><<<dim3(DF / 128, NSEQ / 128), 256, HGEMM_SMEM>>>(
            Xc, Wc + OFF_W1 + (size_t)i * DF * D_, b1 + i * DF, nullptr, nullptr, HIDc, NSEQ, DF, D_);
        hgemm_k<0,0,__half,__half><<<dim3(D_ / 128, NSEQ / 128), 256, HGEMM_SMEM>>>(
            HIDc, Wc + OFF_W2 + (size_t)i * D_ * DF, b2 + i * D_, Xc, nullptr, PRE, NSEQ, D_, DF);
        ln_k<<<NSEQ / 8, 256>>>(PRE, ln2g + i * D_, ln2b + i * D_, Xc);
    }

    head_k<<<NSEQ, 256>>>(Xc, Wp, bp, Wv, bv, out);
}